// round 8
// baseline (speedup 1.0000x reference)
#include <cuda_runtime.h>
#include <cuda_bf16.h>
#include <cstdint>

// ============================================================================
// Edge-MLP via algebraic split:
//   concat(f_s,f_d) @ W1^T == f_s @ W1a^T + f_d @ W1b^T
// Pass 1: persistent node GEMM -> bf16 tables g_P (+b1 folded), g_Q;
//         chunked smem-staged coalesced copy-out.
// Pass 2: 32 warps/CTA, warp-autonomous 3-stage cp.async pipelines (4 edges
//         per batch = one 32-lane pass), packed bf16x2 epilogue.
// ============================================================================

#define MAX_NODES 100000
#define HDIM 128
#define NSM 148

__device__ __nv_bfloat16 g_P[(size_t)MAX_NODES * HDIM];   // P + b1 (bf16)
__device__ __nv_bfloat16 g_Q[(size_t)MAX_NODES * HDIM];

// ---- pass-1 smem layout ----
#define SA      272u                        // bf16 row: 256 B + 16 pad
#define RAWS    528u                        // fp32 row: 512 B + 16 pad
#define OFF_W   0u                          // 256 x 128 bf16 Wcat
#define OFF_A   (256u * SA)                 // 69632
#define OFF_RAW (OFF_A + 128u * SA)         // 104448
#define OFF_B1  (OFF_RAW + 128u * RAWS)     // 172032: float[128]
#define OFF_STG (OFF_B1 + 512u)             // 172544: 32 rows x 528 B stage
#define GEMM_SMEM (OFF_STG + 32u * 528u)    // 189440

// ---- pass-2 smem: per-warp ring (pad restored: 528 stride) ----
#define WTILE    4
#define WSTAGES  3
#define ESTRIDE  528u                       // P 256 | Q 256 | pad 16
#define WSTAGE_B (WTILE * ESTRIDE)          // 2112
#define WRING_B  (WSTAGES * WSTAGE_B)       // 6336
#define NWARPS   32
#define OFF_W2S  ((uint32_t)NWARPS * WRING_B)   // 202752: 8 rows x 144 B (w2)
#define EDGE_SMEM (OFF_W2S + 1216u)         // 203968

// ---------------------------------------------------------------------------
__device__ __forceinline__ uint32_t smem_u32(const void* p) {
    uint32_t a;
    asm("{ .reg .u64 t; cvta.to.shared.u64 t, %1; cvt.u32.u64 %0, t; }" : "=r"(a) : "l"(p));
    return a;
}
__device__ __forceinline__ void cp_async16(uint32_t saddr, const void* gaddr) {
    asm volatile("cp.async.cg.shared.global [%0], [%1], 16;"
                 :: "r"(saddr), "l"(gaddr) : "memory");
}
__device__ __forceinline__ void cp_commit() {
    asm volatile("cp.async.commit_group;" ::: "memory");
}
template <int N>
__device__ __forceinline__ void cp_wait() {
    asm volatile("cp.async.wait_group %0;" :: "n"(N) : "memory");
}
__device__ __forceinline__ void ldsm_x4(uint32_t* r, uint32_t addr) {
    asm volatile("ldmatrix.sync.aligned.m8n8.x4.shared.b16 {%0,%1,%2,%3}, [%4];"
                 : "=r"(r[0]), "=r"(r[1]), "=r"(r[2]), "=r"(r[3]) : "r"(addr));
}
__device__ __forceinline__ void mma_bf16(float* c, const uint32_t* a,
                                         uint32_t b0, uint32_t b1) {
    asm volatile(
        "mma.sync.aligned.m16n8k16.row.col.f32.bf16.bf16.f32 "
        "{%0,%1,%2,%3}, {%4,%5,%6,%7}, {%8,%9}, {%0,%1,%2,%3};"
        : "+f"(c[0]), "+f"(c[1]), "+f"(c[2]), "+f"(c[3])
        : "r"(a[0]), "r"(a[1]), "r"(a[2]), "r"(a[3]), "r"(b0), "r"(b1));
}

// ---------------------------------------------------------------------------
// Pass 1: persistent node GEMM. cp.async A prefetch; b1 folded into P;
// chunked staged copy-out (coalesced 16-B STG).
// ---------------------------------------------------------------------------
__device__ __forceinline__ void issue_raw(uint32_t sb, const float* __restrict__ feats,
                                          int row0, int nNodes) {
    int tid = threadIdx.x;
#pragma unroll
    for (int it = 0; it < 8; it++) {
        int idx = it * 512 + tid;
        int r = idx >> 5, c = idx & 31;
        int node = row0 + r; if (node >= nNodes) node = nNodes - 1;
        cp_async16(sb + OFF_RAW + (uint32_t)r * RAWS + (uint32_t)c * 16u,
                   (const char*)(feats + (size_t)node * HDIM) + c * 16);
    }
    cp_commit();
}

__global__ __launch_bounds__(512, 1) void node_gemm_kernel(
    const float* __restrict__ feats, const float* __restrict__ W1,
    const float* __restrict__ b1, int nNodes)
{
    extern __shared__ char sm[];
    uint32_t sb = smem_u32(sm);
    int tid = threadIdx.x, wid = tid >> 5, lid = tid & 31;
    int ntiles = (nNodes + 127) / 128;

    if (blockIdx.x < ntiles)
        issue_raw(sb, feats, blockIdx.x * 128, nNodes);

    if (tid < 128) ((float*)(sm + OFF_B1))[tid] = b1[tid];

    for (int idx = tid; idx < 256 * 64; idx += 512) {
        int j = idx >> 6, c2 = idx & 63;
        const float* wrow = W1 + (size_t)(j & 127) * 256 + ((j >> 7) << 7);
        float2 v = *(const float2*)(wrow + c2 * 2);
        *(__nv_bfloat162*)(sm + OFF_W + (uint32_t)j * SA + (uint32_t)c2 * 4u) =
            __floats2bfloat162_rn(v.x, v.y);
    }

    int mw = wid & 3, nw = wid >> 2;
    int mbase = mw * 32, nbase = nw * 64;
    uint32_t a_lane = sb + OFF_A +
        (uint32_t)((mbase + (lid & 15)) * SA + ((lid >> 4) * 8) * 2);
    uint32_t b_lane = sb + OFF_W +
        (uint32_t)((nbase + (lid & 7) + ((lid >> 4) << 3)) * SA +
                   (((lid >> 3) & 1) * 8) * 2);

    for (int t = blockIdx.x; t < ntiles; t += NSM) {
        int row0 = t * 128;
        cp_wait<0>();
        __syncthreads();
        for (int idx = tid; idx < 8192; idx += 512) {
            int r = idx >> 6, c2 = idx & 63;
            float2 v = *(const float2*)(sm + OFF_RAW + (uint32_t)r * RAWS + (uint32_t)c2 * 8u);
            *(__nv_bfloat162*)(sm + OFF_A + (uint32_t)r * SA + (uint32_t)c2 * 4u) =
                __floats2bfloat162_rn(v.x, v.y);
        }
        __syncthreads();
        if (t + NSM < ntiles)
            issue_raw(sb, feats, (t + NSM) * 128, nNodes);

        float acc[2][8][4];
#pragma unroll
        for (int mt = 0; mt < 2; mt++)
#pragma unroll
            for (int nt = 0; nt < 8; nt++)
#pragma unroll
                for (int q = 0; q < 4; q++) acc[mt][nt][q] = 0.f;

#pragma unroll
        for (int ks = 0; ks < 8; ks++) {
            uint32_t koff = (uint32_t)ks * 32u;
            uint32_t a[2][4], b[4][4];
#pragma unroll
            for (int u = 0; u < 2; u++)
                ldsm_x4(a[u], a_lane + koff + (uint32_t)u * (16u * SA));
#pragma unroll
            for (int u = 0; u < 4; u++)
                ldsm_x4(b[u], b_lane + koff + (uint32_t)u * (16u * SA));
#pragma unroll
            for (int mt = 0; mt < 2; mt++)
#pragma unroll
                for (int nt = 0; nt < 8; nt++) {
                    int bt = nt >> 1, hi = (nt & 1) << 1;
                    mma_bf16(acc[mt][nt], a[mt], b[bt][hi], b[bt][hi + 1]);
                }
        }

        // ---- chunked staged copy-out: 4 chunks of 32 rows ----
        const float* b1s = (const float*)(sm + OFF_B1);
#pragma unroll
        for (int cp = 0; cp < 4; cp++) {
            __syncthreads();
            if (mw == cp) {
#pragma unroll
                for (int mt = 0; mt < 2; mt++)
#pragma unroll
                    for (int nt = 0; nt < 8; nt++) {
                        int rl = mt * 16 + (lid >> 2);
                        int c0 = nbase + nt * 8 + 2 * (lid & 3);
                        int isP = (c0 < 128);
                        int cc = c0 & 127;
                        float bA = isP ? b1s[cc] : 0.f;
                        float bB = isP ? b1s[cc + 1] : 0.f;
                        const float* c = acc[mt][nt];
                        *(__nv_bfloat162*)(sm + OFF_STG + (uint32_t)rl * 528u + (uint32_t)c0 * 2u) =
                            __floats2bfloat162_rn(c[0] + bA, c[1] + bB);
                        *(__nv_bfloat162*)(sm + OFF_STG + (uint32_t)(rl + 8) * 528u + (uint32_t)c0 * 2u) =
                            __floats2bfloat162_rn(c[2] + bA, c[3] + bB);
                    }
            }
            __syncthreads();
            int nodebase = row0 + cp * 32;
#pragma unroll
            for (int it = 0; it < 2; it++) {
                int idx = it * 512 + tid;          // 1024 16-B chunks
                int r = idx >> 5, c = idx & 31;
                int node = nodebase + r;
                if (node < nNodes) {
                    uint4 v = *(const uint4*)(sm + OFF_STG + (uint32_t)r * 528u + (uint32_t)c * 16u);
                    __nv_bfloat16* dstb = (c < 16 ? g_P : g_Q) + (size_t)node * HDIM + (c & 15) * 8;
                    *(uint4*)dstb = v;
                }
            }
        }
    }
}

// ---------------------------------------------------------------------------
// Pass 2: 32 warps/CTA, warp-autonomous pipelines, packed bf16 epilogue.
// ---------------------------------------------------------------------------
__device__ __forceinline__ int load_idx(const int* __restrict__ src,
                                        const int* __restrict__ dst,
                                        int e0, int E, int lid) {
    int l = lid & 7;
    int e = e0 + (l & 3); if (e >= E) e = E - 1;
    return (l < 4) ? __ldg(src + e) : __ldg(dst + e);
}

__device__ __forceinline__ void fill_batch(uint32_t wbase, int s, int idxreg, int lid) {
    int isQ = lid >> 4;                 // lanes 0-15: P, 16-31: Q
    int q = lid & 15;
    const __nv_bfloat16* tab = isQ ? g_Q : g_P;
    uint32_t sp0 = wbase + (uint32_t)s * WSTAGE_B + (uint32_t)(isQ << 8) + (uint32_t)q * 16u;
#pragma unroll
    for (int it = 0; it < WTILE; it++) {
        int node = __shfl_sync(0xFFFFFFFF, idxreg, it + (isQ << 2));
        cp_async16(sp0 + (uint32_t)it * ESTRIDE,
                   (const char*)(tab + (size_t)node * HDIM) + q * 16);
    }
    cp_commit();
}

__global__ __launch_bounds__(1024, 1) void edge_kernel(
    const int* __restrict__ src, const int* __restrict__ dst,
    const float* __restrict__ W2, const float* __restrict__ b2,
    float* __restrict__ out, int E)
{
    extern __shared__ char sm[];
    uint32_t sb = smem_u32(sm);
    int tid = threadIdx.x, wid = tid >> 5, lid = tid & 31;
    int g = lid & 7, sub = lid >> 3;

    // w2 bank-staggered: 8 rows x 16 floats, row stride 144 B (conflict-free)
    if (tid < 128) {
        int r = tid >> 4, c = tid & 15;
        *(float*)(sm + OFF_W2S + (uint32_t)r * 144u + (uint32_t)c * 4u) = W2[tid];
    }
    float b2v = __ldg(b2);
    __syncthreads();

    const int NW = NSM * NWARPS;
    int warp_g = blockIdx.x * NWARPS + wid;
    int NBat = (E + WTILE - 1) / WTILE;
    int nb = (warp_g < NBat) ? ((NBat - warp_g - 1) / NW + 1) : 0;
    uint32_t wbase = sb + (uint32_t)wid * WRING_B;
    const float* w2row = (const float*)(sm + OFF_W2S + (uint32_t)g * 144u);

    if (nb > 0) fill_batch(wbase, 0, load_idx(src, dst, warp_g * WTILE, E, lid), lid);
    if (nb > 1) fill_batch(wbase, 1, load_idx(src, dst, (warp_g + NW) * WTILE, E, lid), lid);
    int idxA = (nb > 2) ? load_idx(src, dst, (warp_g + 2 * NW) * WTILE, E, lid) : 0;
    int idxB = (nb > 3) ? load_idx(src, dst, (warp_g + 3 * NW) * WTILE, E, lid) : 0;

    int s = 0;
    for (int k = 0; k < nb; k++) {
        int e0 = (warp_g + k * NW) * WTILE;
        if (k + 2 < nb) {
            int sn = s + 2; if (sn >= WSTAGES) sn -= WSTAGES;
            fill_batch(wbase, sn, (k & 1) ? idxB : idxA, lid);
            if (k + 4 < nb) {
                int nidx = load_idx(src, dst, (warp_g + (k + 4) * NW) * WTILE, E, lid);
                if (k & 1) idxB = nidx; else idxA = nidx;
            }
            cp_wait<2>();
        } else if (k + 2 == nb) {
            cp_wait<1>();
        } else {
            cp_wait<0>();
        }
        __syncwarp();

        // one pass: 4 edges x 8 col-groups = 32 lanes
        const char* row = sm + (size_t)wid * WRING_B + (size_t)s * WSTAGE_B +
                          (uint32_t)sub * ESTRIDE + (uint32_t)g * 32u;
        uint4 pv0 = *(const uint4*)(row);
        uint4 pv1 = *(const uint4*)(row + 16);
        uint4 qv0 = *(const uint4*)(row + 256);
        uint4 qv1 = *(const uint4*)(row + 272);
        float4 w0 = *(const float4*)(w2row);
        float4 w1 = *(const float4*)(w2row + 4);
        float4 w2a = *(const float4*)(w2row + 8);
        float4 w3 = *(const float4*)(w2row + 12);

        const __nv_bfloat162 zero2 = __floats2bfloat162_rn(0.f, 0.f);
        const uint32_t* pu = (const uint32_t*)&pv0;
        const uint32_t* qu = (const uint32_t*)&qv0;
        const uint32_t* pu2 = (const uint32_t*)&pv1;
        const uint32_t* qu2 = (const uint32_t*)&qv1;
        float acc = 0.f;
        const float* wv = (const float*)&w0;   // w0..w3 contiguous? no — index per block
        float wf[16] = {w0.x, w0.y, w0.z, w0.w, w1.x, w1.y, w1.z, w1.w,
                        w2a.x, w2a.y, w2a.z, w2a.w, w3.x, w3.y, w3.z, w3.w};
        (void)wv;
#pragma unroll
        for (int i = 0; i < 4; i++) {
            __nv_bfloat162 h = __hmax2(
                __hadd2(*(const __nv_bfloat162*)&pu[i], *(const __nv_bfloat162*)&qu[i]), zero2);
            float2 hf = __bfloat1622float2(h);
            acc = fmaf(hf.x, wf[2 * i], acc);
            acc = fmaf(hf.y, wf[2 * i + 1], acc);
        }
#pragma unroll
        for (int i = 0; i < 4; i++) {
            __nv_bfloat162 h = __hmax2(
                __hadd2(*(const __nv_bfloat162*)&pu2[i], *(const __nv_bfloat162*)&qu2[i]), zero2);
            float2 hf = __bfloat1622float2(h);
            acc = fmaf(hf.x, wf[8 + 2 * i], acc);
            acc = fmaf(hf.y, wf[8 + 2 * i + 1], acc);
        }
#pragma unroll
        for (int d = 1; d <= 4; d <<= 1)
            acc += __shfl_xor_sync(0xFFFFFFFF, acc, d);
        if (g == 0) {
            int e = e0 + sub;
            if (e < E)
                out[e] = 1.f / (1.f + __expf(-(acc + b2v)));
        }
        __syncwarp();
        if (++s >= WSTAGES) s = 0;
    }
}

// ---------------------------------------------------------------------------
extern "C" void kernel_launch(void* const* d_in, const int* in_sizes, int n_in,
                              void* d_out, int out_size) {
    const int*   src   = (const int*)d_in[0];
    const int*   dst   = (const int*)d_in[1];
    const float* feats = (const float*)d_in[2];
    const float* W1    = (const float*)d_in[3];
    const float* b1    = (const float*)d_in[4];
    const float* W2    = (const float*)d_in[5];
    const float* b2    = (const float*)d_in[6];
    float* out = (float*)d_out;
    int E = in_sizes[0];
    int nNodes = in_sizes[2] / HDIM;

    cudaFuncSetAttribute(node_gemm_kernel,
                         cudaFuncAttributeMaxDynamicSharedMemorySize, GEMM_SMEM);
    node_gemm_kernel<<<NSM, 512, GEMM_SMEM>>>(feats, W1, b1, nNodes);

    cudaFuncSetAttribute(edge_kernel,
                         cudaFuncAttributeMaxDynamicSharedMemorySize, EDGE_SMEM);
    edge_kernel<<<NSM, 1024, EDGE_SMEM>>>(src, dst, W2, b2, out, E);
}

// round 11
// speedup vs baseline: 1.4169x; 1.4169x over previous
#include <cuda_runtime.h>
#include <cuda_bf16.h>
#include <cstdint>

// ============================================================================
// Edge-MLP via algebraic split:
//   concat(f_s,f_d) @ W1^T == f_s @ W1a^T + f_d @ W1b^T
// Pass 1: persistent node GEMM -> bf16 tables g_P (+b1 folded), g_Q.
// Pass 2: direct-LDG edge kernel: no smem, no sync. 8 lanes/edge, full-128B
//         coalesced LDG.nc.128, shfl-distributed indices.
// ============================================================================

#define MAX_NODES 100000
#define HDIM 128
#define NSM 148

__device__ __nv_bfloat16 g_P[(size_t)MAX_NODES * HDIM];   // P + b1 (bf16)
__device__ __nv_bfloat16 g_Q[(size_t)MAX_NODES * HDIM];

// ---- pass-1 smem layout ----
#define SA      272u                        // bf16 row: 256 B + 16 pad
#define RAWS    528u                        // fp32 row: 512 B + 16 pad
#define OFF_W   0u                          // 256 x 128 bf16 Wcat
#define OFF_A   (256u * SA)                 // 69632
#define OFF_RAW (OFF_A + 128u * SA)         // 104448
#define OFF_B1  (OFF_RAW + 128u * RAWS)     // 172032: float[128]
#define GEMM_SMEM (OFF_B1 + 512u)           // 172544

// ---------------------------------------------------------------------------
__device__ __forceinline__ uint32_t smem_u32(const void* p) {
    uint32_t a;
    asm("{ .reg .u64 t; cvta.to.shared.u64 t, %1; cvt.u32.u64 %0, t; }" : "=r"(a) : "l"(p));
    return a;
}
__device__ __forceinline__ void cp_async16(uint32_t saddr, const void* gaddr) {
    asm volatile("cp.async.cg.shared.global [%0], [%1], 16;"
                 :: "r"(saddr), "l"(gaddr) : "memory");
}
__device__ __forceinline__ void cp_commit() {
    asm volatile("cp.async.commit_group;" ::: "memory");
}
template <int N>
__device__ __forceinline__ void cp_wait() {
    asm volatile("cp.async.wait_group %0;" :: "n"(N) : "memory");
}
__device__ __forceinline__ void ldsm_x4(uint32_t* r, uint32_t addr) {
    asm volatile("ldmatrix.sync.aligned.m8n8.x4.shared.b16 {%0,%1,%2,%3}, [%4];"
                 : "=r"(r[0]), "=r"(r[1]), "=r"(r[2]), "=r"(r[3]) : "r"(addr));
}
__device__ __forceinline__ void mma_bf16(float* c, const uint32_t* a,
                                         uint32_t b0, uint32_t b1) {
    asm volatile(
        "mma.sync.aligned.m16n8k16.row.col.f32.bf16.bf16.f32 "
        "{%0,%1,%2,%3}, {%4,%5,%6,%7}, {%8,%9}, {%0,%1,%2,%3};"
        : "+f"(c[0]), "+f"(c[1]), "+f"(c[2]), "+f"(c[3])
        : "r"(a[0]), "r"(a[1]), "r"(a[2]), "r"(a[3]), "r"(b0), "r"(b1));
}
// read-only 16-B global load (standard .nc path; portable)
__device__ __forceinline__ void ldg128_nc(uint4& v, const void* p) {
    asm("ld.global.nc.v4.u32 {%0,%1,%2,%3}, [%4];"
        : "=r"(v.x), "=r"(v.y), "=r"(v.z), "=r"(v.w) : "l"(p));
}

// ---------------------------------------------------------------------------
// Pass 1: persistent node GEMM. cp.async A prefetch; b1 folded into P;
// direct bf16x2 copy-out.
// ---------------------------------------------------------------------------
__device__ __forceinline__ void issue_raw(uint32_t sb, const float* __restrict__ feats,
                                          int row0, int nNodes) {
    int tid = threadIdx.x;
#pragma unroll
    for (int it = 0; it < 8; it++) {
        int idx = it * 512 + tid;
        int r = idx >> 5, c = idx & 31;
        int node = row0 + r; if (node >= nNodes) node = nNodes - 1;
        cp_async16(sb + OFF_RAW + (uint32_t)r * RAWS + (uint32_t)c * 16u,
                   (const char*)(feats + (size_t)node * HDIM) + c * 16);
    }
    cp_commit();
}

__global__ __launch_bounds__(512, 1) void node_gemm_kernel(
    const float* __restrict__ feats, const float* __restrict__ W1,
    const float* __restrict__ b1, int nNodes)
{
    extern __shared__ char sm[];
    uint32_t sb = smem_u32(sm);
    int tid = threadIdx.x, wid = tid >> 5, lid = tid & 31;
    int ntiles = (nNodes + 127) / 128;

    if (blockIdx.x < ntiles)
        issue_raw(sb, feats, blockIdx.x * 128, nNodes);

    if (tid < 128) ((float*)(sm + OFF_B1))[tid] = b1[tid];

    for (int idx = tid; idx < 256 * 64; idx += 512) {
        int j = idx >> 6, c2 = idx & 63;
        const float* wrow = W1 + (size_t)(j & 127) * 256 + ((j >> 7) << 7);
        float2 v = *(const float2*)(wrow + c2 * 2);
        *(__nv_bfloat162*)(sm + OFF_W + (uint32_t)j * SA + (uint32_t)c2 * 4u) =
            __floats2bfloat162_rn(v.x, v.y);
    }

    int mw = wid & 3, nw = wid >> 2;
    int mbase = mw * 32, nbase = nw * 64;
    uint32_t a_lane = sb + OFF_A +
        (uint32_t)((mbase + (lid & 15)) * SA + ((lid >> 4) * 8) * 2);
    uint32_t b_lane = sb + OFF_W +
        (uint32_t)((nbase + (lid & 7) + ((lid >> 4) << 3)) * SA +
                   (((lid >> 3) & 1) * 8) * 2);

    for (int t = blockIdx.x; t < ntiles; t += NSM) {
        int row0 = t * 128;
        cp_wait<0>();
        __syncthreads();
        for (int idx = tid; idx < 8192; idx += 512) {
            int r = idx >> 6, c2 = idx & 63;
            float2 v = *(const float2*)(sm + OFF_RAW + (uint32_t)r * RAWS + (uint32_t)c2 * 8u);
            *(__nv_bfloat162*)(sm + OFF_A + (uint32_t)r * SA + (uint32_t)c2 * 4u) =
                __floats2bfloat162_rn(v.x, v.y);
        }
        __syncthreads();
        if (t + NSM < ntiles)
            issue_raw(sb, feats, (t + NSM) * 128, nNodes);

        float acc[2][8][4];
#pragma unroll
        for (int mt = 0; mt < 2; mt++)
#pragma unroll
            for (int nt = 0; nt < 8; nt++)
#pragma unroll
                for (int q = 0; q < 4; q++) acc[mt][nt][q] = 0.f;

#pragma unroll
        for (int ks = 0; ks < 8; ks++) {
            uint32_t koff = (uint32_t)ks * 32u;
            uint32_t a[2][4], b[4][4];
#pragma unroll
            for (int u = 0; u < 2; u++)
                ldsm_x4(a[u], a_lane + koff + (uint32_t)u * (16u * SA));
#pragma unroll
            for (int u = 0; u < 4; u++)
                ldsm_x4(b[u], b_lane + koff + (uint32_t)u * (16u * SA));
#pragma unroll
            for (int mt = 0; mt < 2; mt++)
#pragma unroll
                for (int nt = 0; nt < 8; nt++) {
                    int bt = nt >> 1, hi = (nt & 1) << 1;
                    mma_bf16(acc[mt][nt], a[mt], b[bt][hi], b[bt][hi + 1]);
                }
        }

        // copy-out: cols<128 -> g_P (+b1), cols>=128 -> g_Q
        const float* b1s = (const float*)(sm + OFF_B1);
#pragma unroll
        for (int mt = 0; mt < 2; mt++)
#pragma unroll
            for (int nt = 0; nt < 8; nt++) {
                int r = mbase + mt * 16 + (lid >> 2);
                int c0 = nbase + nt * 8 + 2 * (lid & 3);
                int isP = (c0 < 128);
                int cc = c0 & 127;
                float bA = isP ? b1s[cc] : 0.f;
                float bB = isP ? b1s[cc + 1] : 0.f;
                __nv_bfloat16* base = isP ? g_P : g_Q;
                const float* c = acc[mt][nt];
                int n0 = row0 + r, n1 = row0 + r + 8;
                if (n0 < nNodes)
                    *(__nv_bfloat162*)(base + (size_t)n0 * HDIM + cc) =
                        __floats2bfloat162_rn(c[0] + bA, c[1] + bB);
                if (n1 < nNodes)
                    *(__nv_bfloat162*)(base + (size_t)n1 * HDIM + cc) =
                        __floats2bfloat162_rn(c[2] + bA, c[3] + bB);
            }
    }
}

// ---------------------------------------------------------------------------
// Pass 2: direct-LDG edge kernel. Warp = 8 edges (2 independent groups of 4).
// Lane (sub,g): edge sub-of-4, 16-B chunk g. Each LDG.128 covers 4 full
// contiguous 128-B segments (perfect wavefronts). No smem, no barriers.
// ---------------------------------------------------------------------------
#define EW_WARPS 8   // 256-thr blocks

__global__ __launch_bounds__(256) void edge_kernel(
    const int* __restrict__ src, const int* __restrict__ dst,
    const float* __restrict__ W2, const float* __restrict__ b2,
    float* __restrict__ out, int E)
{
    int tid = threadIdx.x, wid = tid >> 5, lid = tid & 31;
    int g = lid & 7, sub = lid >> 3;

    int e0 = (blockIdx.x * EW_WARPS + wid) * 8;
    if (e0 >= E) return;

    // w2: chunk 0 covers cols [g*8, g*8+8), chunk 1 covers [64+g*8, ...)
    float wlo[8], whi[8];
#pragma unroll
    for (int i = 0; i < 4; i++) {
        float2 a = *(const float2*)(W2 + g * 8 + 2 * i);
        float2 b = *(const float2*)(W2 + 64 + g * 8 + 2 * i);
        wlo[2 * i] = a.x; wlo[2 * i + 1] = a.y;
        whi[2 * i] = b.x; whi[2 * i + 1] = b.y;
    }
    float b2v = __ldg(b2);

    // one warp-wide index load: lanes 0-7 src, 8-15 dst (16-31 duplicate)
    int l = lid & 15;
    int ee = e0 + (l & 7); if (ee >= E) ee = E - 1;
    int idx = (l < 8) ? __ldg(src + ee) : __ldg(dst + ee);

    // issue all 8 independent LDG.128 per group pair (MLP=8)
    uint4 pv[2][2], qv[2][2];
#pragma unroll
    for (int b = 0; b < 2; b++) {
        int sN = __shfl_sync(0xFFFFFFFF, idx, b * 4 + sub);
        int dN = __shfl_sync(0xFFFFFFFF, idx, 8 + b * 4 + sub);
        const char* pb = (const char*)(g_P + (size_t)sN * HDIM);
        const char* qb = (const char*)(g_Q + (size_t)dN * HDIM);
        ldg128_nc(pv[b][0], pb + g * 16);
        ldg128_nc(pv[b][1], pb + 128 + g * 16);
        ldg128_nc(qv[b][0], qb + g * 16);
        ldg128_nc(qv[b][1], qb + 128 + g * 16);
    }

    const __nv_bfloat162 zero2 = __floats2bfloat162_rn(0.f, 0.f);
#pragma unroll
    for (int b = 0; b < 2; b++) {
        float acc = 0.f;
        const uint32_t* plo = (const uint32_t*)&pv[b][0];
        const uint32_t* qlo = (const uint32_t*)&qv[b][0];
        const uint32_t* phi = (const uint32_t*)&pv[b][1];
        const uint32_t* qhi = (const uint32_t*)&qv[b][1];
#pragma unroll
        for (int i = 0; i < 4; i++) {
            __nv_bfloat162 h = __hmax2(
                __hadd2(*(const __nv_bfloat162*)&plo[i],
                        *(const __nv_bfloat162*)&qlo[i]), zero2);
            float2 hf = __bfloat1622float2(h);
            acc = fmaf(hf.x, wlo[2 * i], acc);
            acc = fmaf(hf.y, wlo[2 * i + 1], acc);
        }
#pragma unroll
        for (int i = 0; i < 4; i++) {
            __nv_bfloat162 h = __hmax2(
                __hadd2(*(const __nv_bfloat162*)&phi[i],
                        *(const __nv_bfloat162*)&qhi[i]), zero2);
            float2 hf = __bfloat1622float2(h);
            acc = fmaf(hf.x, whi[2 * i], acc);
            acc = fmaf(hf.y, whi[2 * i + 1], acc);
        }
#pragma unroll
        for (int d = 1; d <= 4; d <<= 1)
            acc += __shfl_xor_sync(0xFFFFFFFF, acc, d);
        if (g == 0) {
            int e = e0 + b * 4 + sub;
            if (e < E)
                out[e] = 1.f / (1.f + __expf(-(acc + b2v)));
        }
    }
}

// ---------------------------------------------------------------------------
extern "C" void kernel_launch(void* const* d_in, const int* in_sizes, int n_in,
                              void* d_out, int out_size) {
    const int*   src   = (const int*)d_in[0];
    const int*   dst   = (const int*)d_in[1];
    const float* feats = (const float*)d_in[2];
    const float* W1    = (const float*)d_in[3];
    const float* b1    = (const float*)d_in[4];
    const float* W2    = (const float*)d_in[5];
    const float* b2    = (const float*)d_in[6];
    float* out = (float*)d_out;
    int E = in_sizes[0];
    int nNodes = in_sizes[2] / HDIM;

    cudaFuncSetAttribute(node_gemm_kernel,
                         cudaFuncAttributeMaxDynamicSharedMemorySize, GEMM_SMEM);
    node_gemm_kernel<<<NSM, 512, GEMM_SMEM>>>(feats, W1, b1, nNodes);

    int epb = EW_WARPS * 8;   // edges per block
    edge_kernel<<<(E + epb - 1) / epb, EW_WARPS * 32>>>(src, dst, W2, b2, out, E);
}

// round 12
// speedup vs baseline: 1.4935x; 1.0540x over previous
#include <cuda_runtime.h>
#include <cuda_bf16.h>
#include <cstdint>

// ============================================================================
// Edge-MLP via algebraic split:
//   concat(f_s,f_d) @ W1^T == f_s @ W1a^T + f_d @ W1b^T
// Pass 1: persistent node GEMM, 64-row tiles, register-prefetched A
//         (LDG.128 fp32 -> cvt in regs -> STS bf16), b1 folded into P.
// Pass 2: direct-LDG edge kernel (unchanged from R11).
// ============================================================================

#define MAX_NODES 100000
#define HDIM 128
#define NSM 148
#define TROWS 64

__device__ __nv_bfloat16 g_P[(size_t)MAX_NODES * HDIM];   // P + b1 (bf16)
__device__ __nv_bfloat16 g_Q[(size_t)MAX_NODES * HDIM];

// ---- pass-1 smem layout ----
#define SA      272u                        // bf16 row: 256 B + 16 pad
#define OFF_W   0u                          // 256 x 128 bf16 Wcat (69632 B)
#define OFF_A   (256u * SA)                 // 69632: 64 x 128 bf16 (17408 B)
#define OFF_B1  (OFF_A + 64u * SA)          // 87040: float[128]
#define GEMM_SMEM (OFF_B1 + 512u)           // 87552

// ---------------------------------------------------------------------------
__device__ __forceinline__ uint32_t smem_u32(const void* p) {
    uint32_t a;
    asm("{ .reg .u64 t; cvta.to.shared.u64 t, %1; cvt.u32.u64 %0, t; }" : "=r"(a) : "l"(p));
    return a;
}
__device__ __forceinline__ void ldsm_x4(uint32_t* r, uint32_t addr) {
    asm volatile("ldmatrix.sync.aligned.m8n8.x4.shared.b16 {%0,%1,%2,%3}, [%4];"
                 : "=r"(r[0]), "=r"(r[1]), "=r"(r[2]), "=r"(r[3]) : "r"(addr));
}
__device__ __forceinline__ void mma_bf16(float* c, const uint32_t* a,
                                         uint32_t b0, uint32_t b1) {
    asm volatile(
        "mma.sync.aligned.m16n8k16.row.col.f32.bf16.bf16.f32 "
        "{%0,%1,%2,%3}, {%4,%5,%6,%7}, {%8,%9}, {%0,%1,%2,%3};"
        : "+f"(c[0]), "+f"(c[1]), "+f"(c[2]), "+f"(c[3])
        : "r"(a[0]), "r"(a[1]), "r"(a[2]), "r"(a[3]), "r"(b0), "r"(b1));
}
// read-only 16-B global load
__device__ __forceinline__ void ldg128_nc(uint4& v, const void* p) {
    asm("ld.global.nc.v4.u32 {%0,%1,%2,%3}, [%4];"
        : "=r"(v.x), "=r"(v.y), "=r"(v.z), "=r"(v.w) : "l"(p));
}
__device__ __forceinline__ void sts64(uint32_t addr, uint32_t lo, uint32_t hi) {
    asm volatile("st.shared.v2.u32 [%0], {%1, %2};" :: "r"(addr), "r"(lo), "r"(hi) : "memory");
}

// ---------------------------------------------------------------------------
// Pass 1: persistent node GEMM. Tile 64 nodes x 256 outs, K=128.
// 16 warps, warp tile m16 x n64. A prefetched into registers.
// ---------------------------------------------------------------------------
__device__ __forceinline__ void prefetch_A(uint4* pf, const float* __restrict__ feats,
                                           int row0, int nNodes) {
    int tid = threadIdx.x;
#pragma unroll
    for (int k = 0; k < 4; k++) {
        int id = k * 512 + tid;            // 2048 16-B chunks (64 rows x 32)
        int r = id >> 5, c = id & 31;
        int node = row0 + r; if (node >= nNodes) node = nNodes - 1;
        ldg128_nc(pf[k], (const char*)(feats + (size_t)node * HDIM) + c * 16);
    }
}

__global__ __launch_bounds__(512, 1) void node_gemm_kernel(
    const float* __restrict__ feats, const float* __restrict__ W1,
    const float* __restrict__ b1, int nNodes)
{
    extern __shared__ char sm[];
    uint32_t sb = smem_u32(sm);
    int tid = threadIdx.x, wid = tid >> 5, lid = tid & 31;
    int ntiles = (nNodes + TROWS - 1) / TROWS;

    uint4 pf[4];
    if (blockIdx.x < ntiles)
        prefetch_A(pf, feats, blockIdx.x * TROWS, nNodes);

    if (tid < 128) ((float*)(sm + OFF_B1))[tid] = b1[tid];

    // W1 -> Wcat bf16 smem, once
    for (int idx = tid; idx < 256 * 64; idx += 512) {
        int j = idx >> 6, c2 = idx & 63;
        const float* wrow = W1 + (size_t)(j & 127) * 256 + ((j >> 7) << 7);
        float2 v = *(const float2*)(wrow + c2 * 2);
        *(__nv_bfloat162*)(sm + OFF_W + (uint32_t)j * SA + (uint32_t)c2 * 4u) =
            __floats2bfloat162_rn(v.x, v.y);
    }

    int mw = wid & 3, nw = wid >> 2;
    int mbase = mw * 16, nbase = nw * 64;
    uint32_t a_lane = sb + OFF_A +
        (uint32_t)((mbase + (lid & 15)) * SA + ((lid >> 4) * 8) * 2);
    uint32_t b_lane = sb + OFF_W +
        (uint32_t)((nbase + (lid & 7) + ((lid >> 4) << 3)) * SA +
                   (((lid >> 3) & 1) * 8) * 2);
    // STS addressing for the A fill
    uint32_t sts_base = sb + OFF_A;
    __syncthreads();

    for (int t = blockIdx.x; t < ntiles; t += NSM) {
        int row0 = t * TROWS;

        // convert prefetched fp32 -> bf16, store to A tile
#pragma unroll
        for (int k = 0; k < 4; k++) {
            int id = k * 512 + tid;
            int r = id >> 5, c = id & 31;
            const float* v = (const float*)&pf[k];
            __nv_bfloat162 lo = __floats2bfloat162_rn(v[0], v[1]);
            __nv_bfloat162 hi = __floats2bfloat162_rn(v[2], v[3]);
            sts64(sts_base + (uint32_t)r * SA + (uint32_t)c * 8u,
                  *(const uint32_t*)&lo, *(const uint32_t*)&hi);
        }
        __syncthreads();

        // prefetch next tile (latency hidden under mma below)
        if (t + NSM < ntiles)
            prefetch_A(pf, feats, (t + NSM) * TROWS, nNodes);

        float acc[8][4];
#pragma unroll
        for (int nt = 0; nt < 8; nt++)
#pragma unroll
            for (int q = 0; q < 4; q++) acc[nt][q] = 0.f;

#pragma unroll
        for (int ks = 0; ks < 8; ks++) {
            uint32_t koff = (uint32_t)ks * 32u;
            uint32_t a[4], b[4][4];
            ldsm_x4(a, a_lane + koff);
#pragma unroll
            for (int u = 0; u < 4; u++)
                ldsm_x4(b[u], b_lane + koff + (uint32_t)u * (16u * SA));
#pragma unroll
            for (int nt = 0; nt < 8; nt++) {
                int bt = nt >> 1, hi = (nt & 1) << 1;
                mma_bf16(acc[nt], a, b[bt][hi], b[bt][hi + 1]);
            }
        }

        // copy-out: cols<128 -> g_P (+b1), cols>=128 -> g_Q
        const float* b1s = (const float*)(sm + OFF_B1);
#pragma unroll
        for (int nt = 0; nt < 8; nt++) {
            int r = mbase + (lid >> 2);
            int c0 = nbase + nt * 8 + 2 * (lid & 3);
            int isP = (c0 < 128);
            int cc = c0 & 127;
            float bA = isP ? b1s[cc] : 0.f;
            float bB = isP ? b1s[cc + 1] : 0.f;
            __nv_bfloat16* base = isP ? g_P : g_Q;
            const float* c = acc[nt];
            int n0 = row0 + r, n1 = row0 + r + 8;
            if (n0 < nNodes)
                *(__nv_bfloat162*)(base + (size_t)n0 * HDIM + cc) =
                    __floats2bfloat162_rn(c[0] + bA, c[1] + bB);
            if (n1 < nNodes)
                *(__nv_bfloat162*)(base + (size_t)n1 * HDIM + cc) =
                    __floats2bfloat162_rn(c[2] + bA, c[3] + bB);
        }
        __syncthreads();   // all warps done with A before next STS
    }
}

// ---------------------------------------------------------------------------
// Pass 2: direct-LDG edge kernel (unchanged from R11).
// ---------------------------------------------------------------------------
#define EW_WARPS 8   // 256-thr blocks

__global__ __launch_bounds__(256) void edge_kernel(
    const int* __restrict__ src, const int* __restrict__ dst,
    const float* __restrict__ W2, const float* __restrict__ b2,
    float* __restrict__ out, int E)
{
    int tid = threadIdx.x, wid = tid >> 5, lid = tid & 31;
    int g = lid & 7, sub = lid >> 3;

    int e0 = (blockIdx.x * EW_WARPS + wid) * 8;
    if (e0 >= E) return;

    float wlo[8], whi[8];
#pragma unroll
    for (int i = 0; i < 4; i++) {
        float2 a = *(const float2*)(W2 + g * 8 + 2 * i);
        float2 b = *(const float2*)(W2 + 64 + g * 8 + 2 * i);
        wlo[2 * i] = a.x; wlo[2 * i + 1] = a.y;
        whi[2 * i] = b.x; whi[2 * i + 1] = b.y;
    }
    float b2v = __ldg(b2);

    int l = lid & 15;
    int ee = e0 + (l & 7); if (ee >= E) ee = E - 1;
    int idx = (l < 8) ? __ldg(src + ee) : __ldg(dst + ee);

    uint4 pv[2][2], qv[2][2];
#pragma unroll
    for (int b = 0; b < 2; b++) {
        int sN = __shfl_sync(0xFFFFFFFF, idx, b * 4 + sub);
        int dN = __shfl_sync(0xFFFFFFFF, idx, 8 + b * 4 + sub);
        const char* pb = (const char*)(g_P + (size_t)sN * HDIM);
        const char* qb = (const char*)(g_Q + (size_t)dN * HDIM);
        ldg128_nc(pv[b][0], pb + g * 16);
        ldg128_nc(pv[b][1], pb + 128 + g * 16);
        ldg128_nc(qv[b][0], qb + g * 16);
        ldg128_nc(qv[b][1], qb + 128 + g * 16);
    }

    const __nv_bfloat162 zero2 = __floats2bfloat162_rn(0.f, 0.f);
#pragma unroll
    for (int b = 0; b < 2; b++) {
        float acc = 0.f;
        const uint32_t* plo = (const uint32_t*)&pv[b][0];
        const uint32_t* qlo = (const uint32_t*)&qv[b][0];
        const uint32_t* phi = (const uint32_t*)&pv[b][1];
        const uint32_t* qhi = (const uint32_t*)&qv[b][1];
#pragma unroll
        for (int i = 0; i < 4; i++) {
            __nv_bfloat162 h = __hmax2(
                __hadd2(*(const __nv_bfloat162*)&plo[i],
                        *(const __nv_bfloat162*)&qlo[i]), zero2);
            float2 hf = __bfloat1622float2(h);
            acc = fmaf(hf.x, wlo[2 * i], acc);
            acc = fmaf(hf.y, wlo[2 * i + 1], acc);
        }
#pragma unroll
        for (int i = 0; i < 4; i++) {
            __nv_bfloat162 h = __hmax2(
                __hadd2(*(const __nv_bfloat162*)&phi[i],
                        *(const __nv_bfloat162*)&qhi[i]), zero2);
            float2 hf = __bfloat1622float2(h);
            acc = fmaf(hf.x, whi[2 * i], acc);
            acc = fmaf(hf.y, whi[2 * i + 1], acc);
        }
#pragma unroll
        for (int d = 1; d <= 4; d <<= 1)
            acc += __shfl_xor_sync(0xFFFFFFFF, acc, d);
        if (g == 0) {
            int e = e0 + b * 4 + sub;
            if (e < E)
                out[e] = 1.f / (1.f + __expf(-(acc + b2v)));
        }
    }
}

// ---------------------------------------------------------------------------
extern "C" void kernel_launch(void* const* d_in, const int* in_sizes, int n_in,
                              void* d_out, int out_size) {
    const int*   src   = (const int*)d_in[0];
    const int*   dst   = (const int*)d_in[1];
    const float* feats = (const float*)d_in[2];
    const float* W1    = (const float*)d_in[3];
    const float* b1    = (const float*)d_in[4];
    const float* W2    = (const float*)d_in[5];
    const float* b2    = (const float*)d_in[6];
    float* out = (float*)d_out;
    int E = in_sizes[0];
    int nNodes = in_sizes[2] / HDIM;

    cudaFuncSetAttribute(node_gemm_kernel,
                         cudaFuncAttributeMaxDynamicSharedMemorySize, GEMM_SMEM);
    node_gemm_kernel<<<NSM, 512, GEMM_SMEM>>>(feats, W1, b1, nNodes);

    int epb = EW_WARPS * 8;   // edges per block
    edge_kernel<<<(E + epb - 1) / epb, EW_WARPS * 32>>>(src, dst, W2, b2, out, E);
}

// round 13
// speedup vs baseline: 1.5356x; 1.0282x over previous
#include <cuda_runtime.h>
#include <cuda_bf16.h>
#include <cstdint>

// ============================================================================
// Edge-MLP via algebraic split:
//   concat(f_s,f_d) @ W1^T == f_s @ W1a^T + f_d @ W1b^T
// Pass 1: persistent node GEMM, 64-row tiles, register-prefetched A,
//         smem-staged coalesced copy-out (STG.128), b1 folded into P.
// Pass 2: direct-LDG edge kernel (frozen since R11).
// ============================================================================

#define MAX_NODES 100000
#define HDIM 128
#define NSM 148
#define TROWS 64

__device__ __nv_bfloat16 g_P[(size_t)MAX_NODES * HDIM];   // P + b1 (bf16)
__device__ __nv_bfloat16 g_Q[(size_t)MAX_NODES * HDIM];

// ---- pass-1 smem layout ----
#define SA      272u                        // bf16 row: 256 B + 16 pad
#define SSTG    528u                        // stage row: 512 B + 16 pad
#define OFF_W   0u                          // 256 x 128 bf16 Wcat (69632 B)
#define OFF_A   (256u * SA)                 // 69632: 64 x 128 bf16 (17408 B)
#define OFF_B1  (OFF_A + 64u * SA)          // 87040: float[128]
#define OFF_STG (OFF_B1 + 512u)             // 87552: 64 x 528 stage (33792 B)
#define GEMM_SMEM (OFF_STG + 64u * SSTG)    // 121344

// ---------------------------------------------------------------------------
__device__ __forceinline__ uint32_t smem_u32(const void* p) {
    uint32_t a;
    asm("{ .reg .u64 t; cvta.to.shared.u64 t, %1; cvt.u32.u64 %0, t; }" : "=r"(a) : "l"(p));
    return a;
}
__device__ __forceinline__ void ldsm_x4(uint32_t* r, uint32_t addr) {
    asm volatile("ldmatrix.sync.aligned.m8n8.x4.shared.b16 {%0,%1,%2,%3}, [%4];"
                 : "=r"(r[0]), "=r"(r[1]), "=r"(r[2]), "=r"(r[3]) : "r"(addr));
}
__device__ __forceinline__ void mma_bf16(float* c, const uint32_t* a,
                                         uint32_t b0, uint32_t b1) {
    asm volatile(
        "mma.sync.aligned.m16n8k16.row.col.f32.bf16.bf16.f32 "
        "{%0,%1,%2,%3}, {%4,%5,%6,%7}, {%8,%9}, {%0,%1,%2,%3};"
        : "+f"(c[0]), "+f"(c[1]), "+f"(c[2]), "+f"(c[3])
        : "r"(a[0]), "r"(a[1]), "r"(a[2]), "r"(a[3]), "r"(b0), "r"(b1));
}
__device__ __forceinline__ void ldg128_nc(uint4& v, const void* p) {
    asm("ld.global.nc.v4.u32 {%0,%1,%2,%3}, [%4];"
        : "=r"(v.x), "=r"(v.y), "=r"(v.z), "=r"(v.w) : "l"(p));
}
__device__ __forceinline__ void sts32(uint32_t addr, uint32_t v) {
    asm volatile("st.shared.u32 [%0], %1;" :: "r"(addr), "r"(v) : "memory");
}
__device__ __forceinline__ void sts64(uint32_t addr, uint32_t lo, uint32_t hi) {
    asm volatile("st.shared.v2.u32 [%0], {%1, %2};" :: "r"(addr), "r"(lo), "r"(hi) : "memory");
}

// ---------------------------------------------------------------------------
// Pass 1: persistent node GEMM. Tile 64 nodes x 256 outs, K=128.
// 16 warps, warp tile m16 x n64. A prefetched into registers.
// ---------------------------------------------------------------------------
__device__ __forceinline__ void prefetch_A(uint4* pf, const float* __restrict__ feats,
                                           int row0, int nNodes) {
    int tid = threadIdx.x;
#pragma unroll
    for (int k = 0; k < 4; k++) {
        int id = k * 512 + tid;            // 2048 16-B chunks (64 rows x 32)
        int r = id >> 5, c = id & 31;
        int node = row0 + r; if (node >= nNodes) node = nNodes - 1;
        ldg128_nc(pf[k], (const char*)(feats + (size_t)node * HDIM) + c * 16);
    }
}

__global__ __launch_bounds__(512, 1) void node_gemm_kernel(
    const float* __restrict__ feats, const float* __restrict__ W1,
    const float* __restrict__ b1, int nNodes)
{
    extern __shared__ char sm[];
    uint32_t sb = smem_u32(sm);
    int tid = threadIdx.x, wid = tid >> 5, lid = tid & 31;
    int ntiles = (nNodes + TROWS - 1) / TROWS;

    uint4 pf[4];
    if (blockIdx.x < ntiles)
        prefetch_A(pf, feats, blockIdx.x * TROWS, nNodes);

    if (tid < 128) ((float*)(sm + OFF_B1))[tid] = b1[tid];

    // W1 -> Wcat bf16 smem, once
    for (int idx = tid; idx < 256 * 64; idx += 512) {
        int j = idx >> 6, c2 = idx & 63;
        const float* wrow = W1 + (size_t)(j & 127) * 256 + ((j >> 7) << 7);
        float2 v = *(const float2*)(wrow + c2 * 2);
        *(__nv_bfloat162*)(sm + OFF_W + (uint32_t)j * SA + (uint32_t)c2 * 4u) =
            __floats2bfloat162_rn(v.x, v.y);
    }

    int mw = wid & 3, nw = wid >> 2;
    int mbase = mw * 16, nbase = nw * 64;
    uint32_t a_lane = sb + OFF_A +
        (uint32_t)((mbase + (lid & 15)) * SA + ((lid >> 4) * 8) * 2);
    uint32_t b_lane = sb + OFF_W +
        (uint32_t)((nbase + (lid & 7) + ((lid >> 4) << 3)) * SA +
                   (((lid >> 3) & 1) * 8) * 2);
    uint32_t sts_base = sb + OFF_A;
    __syncthreads();

    for (int t = blockIdx.x; t < ntiles; t += NSM) {
        int row0 = t * TROWS;

        // convert prefetched fp32 -> bf16, store to A tile
#pragma unroll
        for (int k = 0; k < 4; k++) {
            int id = k * 512 + tid;
            int r = id >> 5, c = id & 31;
            const float* v = (const float*)&pf[k];
            __nv_bfloat162 lo = __floats2bfloat162_rn(v[0], v[1]);
            __nv_bfloat162 hi = __floats2bfloat162_rn(v[2], v[3]);
            sts64(sts_base + (uint32_t)r * SA + (uint32_t)c * 8u,
                  *(const uint32_t*)&lo, *(const uint32_t*)&hi);
        }
        __syncthreads();   // A visible; also: all prev-tile stage reads done

        // prefetch next tile (latency hidden under mma below)
        if (t + NSM < ntiles)
            prefetch_A(pf, feats, (t + NSM) * TROWS, nNodes);

        float acc[8][4];
#pragma unroll
        for (int nt = 0; nt < 8; nt++)
#pragma unroll
            for (int q = 0; q < 4; q++) acc[nt][q] = 0.f;

#pragma unroll
        for (int ks = 0; ks < 8; ks++) {
            uint32_t koff = (uint32_t)ks * 32u;
            uint32_t a[4], b[4][4];
            ldsm_x4(a, a_lane + koff);
#pragma unroll
            for (int u = 0; u < 4; u++)
                ldsm_x4(b[u], b_lane + koff + (uint32_t)u * (16u * SA));
#pragma unroll
            for (int nt = 0; nt < 8; nt++) {
                int bt = nt >> 1, hi = (nt & 1) << 1;
                mma_bf16(acc[nt], a, b[bt][hi], b[bt][hi + 1]);
            }
        }

        // ---- epilogue: STS stage (conflict-free), then coalesced STG.128 ----
        const float* b1s = (const float*)(sm + OFF_B1);
#pragma unroll
        for (int nt = 0; nt < 8; nt++) {
            int r = mbase + (lid >> 2);
            int c0 = nbase + nt * 8 + 2 * (lid & 3);
            int isP = (c0 < 128);
            int cc = c0 & 127;
            float bA = isP ? b1s[cc] : 0.f;
            float bB = isP ? b1s[cc + 1] : 0.f;
            const float* c = acc[nt];
            __nv_bfloat162 v0 = __floats2bfloat162_rn(c[0] + bA, c[1] + bB);
            __nv_bfloat162 v1 = __floats2bfloat162_rn(c[2] + bA, c[3] + bB);
            sts32(sb + OFF_STG + (uint32_t)r * SSTG + (uint32_t)c0 * 2u,
                  *(const uint32_t*)&v0);
            sts32(sb + OFF_STG + (uint32_t)(r + 8) * SSTG + (uint32_t)c0 * 2u,
                  *(const uint32_t*)&v1);
        }
        __syncthreads();   // stage visible

        // coalesced copy-out: 2048 16-B chunks; c<16 -> g_P, c>=16 -> g_Q
#pragma unroll
        for (int it = 0; it < 4; it++) {
            int id = it * 512 + tid;
            int r = id >> 5, c = id & 31;
            int node = row0 + r;
            if (node < nNodes) {
                uint4 v = *(const uint4*)(sm + OFF_STG + (uint32_t)r * SSTG + (uint32_t)c * 16u);
                __nv_bfloat16* dstb = (c < 16 ? g_P : g_Q) + (size_t)node * HDIM + (c & 15) * 8;
                *(uint4*)dstb = v;
            }
        }
        // next iteration's leading syncthreads protects stage reuse
    }
}

// ---------------------------------------------------------------------------
// Pass 2: direct-LDG edge kernel (frozen since R11).
// ---------------------------------------------------------------------------
#define EW_WARPS 8   // 256-thr blocks

__global__ __launch_bounds__(256) void edge_kernel(
    const int* __restrict__ src, const int* __restrict__ dst,
    const float* __restrict__ W2, const float* __restrict__ b2,
    float* __restrict__ out, int E)
{
    int tid = threadIdx.x, wid = tid >> 5, lid = tid & 31;
    int g = lid & 7, sub = lid >> 3;

    int e0 = (blockIdx.x * EW_WARPS + wid) * 8;
    if (e0 >= E) return;

    float wlo[8], whi[8];
#pragma unroll
    for (int i = 0; i < 4; i++) {
        float2 a = *(const float2*)(W2 + g * 8 + 2 * i);
        float2 b = *(const float2*)(W2 + 64 + g * 8 + 2 * i);
        wlo[2 * i] = a.x; wlo[2 * i + 1] = a.y;
        whi[2 * i] = b.x; whi[2 * i + 1] = b.y;
    }
    float b2v = __ldg(b2);

    int l = lid & 15;
    int ee = e0 + (l & 7); if (ee >= E) ee = E - 1;
    int idx = (l < 8) ? __ldg(src + ee) : __ldg(dst + ee);

    uint4 pv[2][2], qv[2][2];
#pragma unroll
    for (int b = 0; b < 2; b++) {
        int sN = __shfl_sync(0xFFFFFFFF, idx, b * 4 + sub);
        int dN = __shfl_sync(0xFFFFFFFF, idx, 8 + b * 4 + sub);
        const char* pb = (const char*)(g_P + (size_t)sN * HDIM);
        const char* qb = (const char*)(g_Q + (size_t)dN * HDIM);
        ldg128_nc(pv[b][0], pb + g * 16);
        ldg128_nc(pv[b][1], pb + 128 + g * 16);
        ldg128_nc(qv[b][0], qb + g * 16);
        ldg128_nc(qv[b][1], qb + 128 + g * 16);
    }

    const __nv_bfloat162 zero2 = __floats2bfloat162_rn(0.f, 0.f);
#pragma unroll
    for (int b = 0; b < 2; b++) {
        float acc = 0.f;
        const uint32_t* plo = (const uint32_t*)&pv[b][0];
        const uint32_t* qlo = (const uint32_t*)&qv[b][0];
        const uint32_t* phi = (const uint32_t*)&pv[b][1];
        const uint32_t* qhi = (const uint32_t*)&qv[b][1];
#pragma unroll
        for (int i = 0; i < 4; i++) {
            __nv_bfloat162 h = __hmax2(
                __hadd2(*(const __nv_bfloat162*)&plo[i],
                        *(const __nv_bfloat162*)&qlo[i]), zero2);
            float2 hf = __bfloat1622float2(h);
            acc = fmaf(hf.x, wlo[2 * i], acc);
            acc = fmaf(hf.y, wlo[2 * i + 1], acc);
        }
#pragma unroll
        for (int i = 0; i < 4; i++) {
            __nv_bfloat162 h = __hmax2(
                __hadd2(*(const __nv_bfloat162*)&phi[i],
                        *(const __nv_bfloat162*)&qhi[i]), zero2);
            float2 hf = __bfloat1622float2(h);
            acc = fmaf(hf.x, whi[2 * i], acc);
            acc = fmaf(hf.y, whi[2 * i + 1], acc);
        }
#pragma unroll
        for (int d = 1; d <= 4; d <<= 1)
            acc += __shfl_xor_sync(0xFFFFFFFF, acc, d);
        if (g == 0) {
            int e = e0 + b * 4 + sub;
            if (e < E)
                out[e] = 1.f / (1.f + __expf(-(acc + b2v)));
        }
    }
}

// ---------------------------------------------------------------------------
extern "C" void kernel_launch(void* const* d_in, const int* in_sizes, int n_in,
                              void* d_out, int out_size) {
    const int*   src   = (const int*)d_in[0];
    const int*   dst   = (const int*)d_in[1];
    const float* feats = (const float*)d_in[2];
    const float* W1    = (const float*)d_in[3];
    const float* b1    = (const float*)d_in[4];
    const float* W2    = (const float*)d_in[5];
    const float* b2    = (const float*)d_in[6];
    float* out = (float*)d_out;
    int E = in_sizes[0];
    int nNodes = in_sizes[2] / HDIM;

    cudaFuncSetAttribute(node_gemm_kernel,
                         cudaFuncAttributeMaxDynamicSharedMemorySize, GEMM_SMEM);
    node_gemm_kernel<<<NSM, 512, GEMM_SMEM>>>(feats, W1, b1, nNodes);

    int epb = EW_WARPS * 8;   // edges per block
    edge_kernel<<<(E + epb - 1) / epb, EW_WARPS * 32>>>(src, dst, W2, b2, out, E);
}

// round 14
// speedup vs baseline: 1.5676x; 1.0208x over previous
#include <cuda_runtime.h>
#include <cuda_bf16.h>
#include <cstdint>

// ============================================================================
// Edge-MLP via algebraic split:
//   concat(f_s,f_d) @ W1^T == f_s @ W1a^T + f_d @ W1b^T
// Pass 1: persistent node GEMM (R13: 64-row tiles, reg-prefetched A, staged
//         coalesced copy-out, b1 folded into P).
// Pass 2: direct-LDG edge kernel, 32 edges/warp batch loop, index prefetch.
// ============================================================================

#define MAX_NODES 100000
#define HDIM 128
#define NSM 148
#define TROWS 64

__device__ __nv_bfloat16 g_P[(size_t)MAX_NODES * HDIM];   // P + b1 (bf16)
__device__ __nv_bfloat16 g_Q[(size_t)MAX_NODES * HDIM];

// ---- pass-1 smem layout ----
#define SA      272u                        // bf16 row: 256 B + 16 pad
#define SSTG    528u                        // stage row: 512 B + 16 pad
#define OFF_W   0u                          // 256 x 128 bf16 Wcat (69632 B)
#define OFF_A   (256u * SA)                 // 69632: 64 x 128 bf16 (17408 B)
#define OFF_B1  (OFF_A + 64u * SA)          // 87040: float[128]
#define OFF_STG (OFF_B1 + 512u)             // 87552: 64 x 528 stage
#define GEMM_SMEM (OFF_STG + 64u * SSTG)    // 121344

// ---------------------------------------------------------------------------
__device__ __forceinline__ uint32_t smem_u32(const void* p) {
    uint32_t a;
    asm("{ .reg .u64 t; cvta.to.shared.u64 t, %1; cvt.u32.u64 %0, t; }" : "=r"(a) : "l"(p));
    return a;
}
__device__ __forceinline__ void ldsm_x4(uint32_t* r, uint32_t addr) {
    asm volatile("ldmatrix.sync.aligned.m8n8.x4.shared.b16 {%0,%1,%2,%3}, [%4];"
                 : "=r"(r[0]), "=r"(r[1]), "=r"(r[2]), "=r"(r[3]) : "r"(addr));
}
__device__ __forceinline__ void mma_bf16(float* c, const uint32_t* a,
                                         uint32_t b0, uint32_t b1) {
    asm volatile(
        "mma.sync.aligned.m16n8k16.row.col.f32.bf16.bf16.f32 "
        "{%0,%1,%2,%3}, {%4,%5,%6,%7}, {%8,%9}, {%0,%1,%2,%3};"
        : "+f"(c[0]), "+f"(c[1]), "+f"(c[2]), "+f"(c[3])
        : "r"(a[0]), "r"(a[1]), "r"(a[2]), "r"(a[3]), "r"(b0), "r"(b1));
}
__device__ __forceinline__ void ldg128_nc(uint4& v, const void* p) {
    asm("ld.global.nc.v4.u32 {%0,%1,%2,%3}, [%4];"
        : "=r"(v.x), "=r"(v.y), "=r"(v.z), "=r"(v.w) : "l"(p));
}
__device__ __forceinline__ void sts32(uint32_t addr, uint32_t v) {
    asm volatile("st.shared.u32 [%0], %1;" :: "r"(addr), "r"(v) : "memory");
}
__device__ __forceinline__ void sts64(uint32_t addr, uint32_t lo, uint32_t hi) {
    asm volatile("st.shared.v2.u32 [%0], {%1, %2};" :: "r"(addr), "r"(lo), "r"(hi) : "memory");
}

// ---------------------------------------------------------------------------
// Pass 1: persistent node GEMM (frozen R13).
// ---------------------------------------------------------------------------
__device__ __forceinline__ void prefetch_A(uint4* pf, const float* __restrict__ feats,
                                           int row0, int nNodes) {
    int tid = threadIdx.x;
#pragma unroll
    for (int k = 0; k < 4; k++) {
        int id = k * 512 + tid;
        int r = id >> 5, c = id & 31;
        int node = row0 + r; if (node >= nNodes) node = nNodes - 1;
        ldg128_nc(pf[k], (const char*)(feats + (size_t)node * HDIM) + c * 16);
    }
}

__global__ __launch_bounds__(512, 1) void node_gemm_kernel(
    const float* __restrict__ feats, const float* __restrict__ W1,
    const float* __restrict__ b1, int nNodes)
{
    extern __shared__ char sm[];
    uint32_t sb = smem_u32(sm);
    int tid = threadIdx.x, wid = tid >> 5, lid = tid & 31;
    int ntiles = (nNodes + TROWS - 1) / TROWS;

    uint4 pf[4];
    if (blockIdx.x < ntiles)
        prefetch_A(pf, feats, blockIdx.x * TROWS, nNodes);

    if (tid < 128) ((float*)(sm + OFF_B1))[tid] = b1[tid];

    for (int idx = tid; idx < 256 * 64; idx += 512) {
        int j = idx >> 6, c2 = idx & 63;
        const float* wrow = W1 + (size_t)(j & 127) * 256 + ((j >> 7) << 7);
        float2 v = *(const float2*)(wrow + c2 * 2);
        *(__nv_bfloat162*)(sm + OFF_W + (uint32_t)j * SA + (uint32_t)c2 * 4u) =
            __floats2bfloat162_rn(v.x, v.y);
    }

    int mw = wid & 3, nw = wid >> 2;
    int mbase = mw * 16, nbase = nw * 64;
    uint32_t a_lane = sb + OFF_A +
        (uint32_t)((mbase + (lid & 15)) * SA + ((lid >> 4) * 8) * 2);
    uint32_t b_lane = sb + OFF_W +
        (uint32_t)((nbase + (lid & 7) + ((lid >> 4) << 3)) * SA +
                   (((lid >> 3) & 1) * 8) * 2);
    uint32_t sts_base = sb + OFF_A;
    __syncthreads();

    for (int t = blockIdx.x; t < ntiles; t += NSM) {
        int row0 = t * TROWS;

#pragma unroll
        for (int k = 0; k < 4; k++) {
            int id = k * 512 + tid;
            int r = id >> 5, c = id & 31;
            const float* v = (const float*)&pf[k];
            __nv_bfloat162 lo = __floats2bfloat162_rn(v[0], v[1]);
            __nv_bfloat162 hi = __floats2bfloat162_rn(v[2], v[3]);
            sts64(sts_base + (uint32_t)r * SA + (uint32_t)c * 8u,
                  *(const uint32_t*)&lo, *(const uint32_t*)&hi);
        }
        __syncthreads();

        if (t + NSM < ntiles)
            prefetch_A(pf, feats, (t + NSM) * TROWS, nNodes);

        float acc[8][4];
#pragma unroll
        for (int nt = 0; nt < 8; nt++)
#pragma unroll
            for (int q = 0; q < 4; q++) acc[nt][q] = 0.f;

#pragma unroll
        for (int ks = 0; ks < 8; ks++) {
            uint32_t koff = (uint32_t)ks * 32u;
            uint32_t a[4], b[4][4];
            ldsm_x4(a, a_lane + koff);
#pragma unroll
            for (int u = 0; u < 4; u++)
                ldsm_x4(b[u], b_lane + koff + (uint32_t)u * (16u * SA));
#pragma unroll
            for (int nt = 0; nt < 8; nt++) {
                int bt = nt >> 1, hi = (nt & 1) << 1;
                mma_bf16(acc[nt], a, b[bt][hi], b[bt][hi + 1]);
            }
        }

        const float* b1s = (const float*)(sm + OFF_B1);
#pragma unroll
        for (int nt = 0; nt < 8; nt++) {
            int r = mbase + (lid >> 2);
            int c0 = nbase + nt * 8 + 2 * (lid & 3);
            int isP = (c0 < 128);
            int cc = c0 & 127;
            float bA = isP ? b1s[cc] : 0.f;
            float bB = isP ? b1s[cc + 1] : 0.f;
            const float* c = acc[nt];
            __nv_bfloat162 v0 = __floats2bfloat162_rn(c[0] + bA, c[1] + bB);
            __nv_bfloat162 v1 = __floats2bfloat162_rn(c[2] + bA, c[3] + bB);
            sts32(sb + OFF_STG + (uint32_t)r * SSTG + (uint32_t)c0 * 2u,
                  *(const uint32_t*)&v0);
            sts32(sb + OFF_STG + (uint32_t)(r + 8) * SSTG + (uint32_t)c0 * 2u,
                  *(const uint32_t*)&v1);
        }
        __syncthreads();

#pragma unroll
        for (int it = 0; it < 4; it++) {
            int id = it * 512 + tid;
            int r = id >> 5, c = id & 31;
            int node = row0 + r;
            if (node < nNodes) {
                uint4 v = *(const uint4*)(sm + OFF_STG + (uint32_t)r * SSTG + (uint32_t)c * 16u);
                __nv_bfloat16* dstb = (c < 16 ? g_P : g_Q) + (size_t)node * HDIM + (c & 15) * 8;
                *(uint4*)dstb = v;
            }
        }
    }
}

// ---------------------------------------------------------------------------
// Pass 2: direct-LDG edge kernel, 32 edges/warp (4 batches of 8), index
// prefetch one batch ahead. w2/b2 loaded once per warp.
// ---------------------------------------------------------------------------
#define EW_WARPS 8    // 256-thr blocks
#define NBATCH   4    // 8-edge batches per warp

__device__ __forceinline__ int load_idx8(const int* __restrict__ src,
                                         const int* __restrict__ dst,
                                         int e0, int E, int lid) {
    int l = lid & 15;
    int e = e0 + (l & 7); if (e >= E) e = E - 1;
    return (l < 8) ? __ldg(src + e) : __ldg(dst + e);
}

__global__ __launch_bounds__(256) void edge_kernel(
    const int* __restrict__ src, const int* __restrict__ dst,
    const float* __restrict__ W2, const float* __restrict__ b2,
    float* __restrict__ out, int E)
{
    int tid = threadIdx.x, wid = tid >> 5, lid = tid & 31;
    int g = lid & 7, sub = lid >> 3;

    int base = (blockIdx.x * EW_WARPS + wid) * (8 * NBATCH);
    if (base >= E) return;

    // w2: chunk 0 covers cols [g*8, g*8+8), chunk 1 covers [64+g*8, ...)
    float wlo[8], whi[8];
#pragma unroll
    for (int i = 0; i < 4; i++) {
        float2 a = *(const float2*)(W2 + g * 8 + 2 * i);
        float2 b = *(const float2*)(W2 + 64 + g * 8 + 2 * i);
        wlo[2 * i] = a.x; wlo[2 * i + 1] = a.y;
        whi[2 * i] = b.x; whi[2 * i + 1] = b.y;
    }
    float b2v = __ldg(b2);

    int idx = load_idx8(src, dst, base, E, lid);
    const __nv_bfloat162 zero2 = __floats2bfloat162_rn(0.f, 0.f);

#pragma unroll
    for (int bt = 0; bt < NBATCH; bt++) {
        int e0 = base + bt * 8;
        if (e0 >= E) break;

        // issue all 8 independent LDG.128 (MLP=8)
        uint4 pv[2][2], qv[2][2];
#pragma unroll
        for (int b = 0; b < 2; b++) {
            int sN = __shfl_sync(0xFFFFFFFF, idx, b * 4 + sub);
            int dN = __shfl_sync(0xFFFFFFFF, idx, 8 + b * 4 + sub);
            const char* pb = (const char*)(g_P + (size_t)sN * HDIM);
            const char* qb = (const char*)(g_Q + (size_t)dN * HDIM);
            ldg128_nc(pv[b][0], pb + g * 16);
            ldg128_nc(pv[b][1], pb + 128 + g * 16);
            ldg128_nc(qv[b][0], qb + g * 16);
            ldg128_nc(qv[b][1], qb + 128 + g * 16);
        }
        // prefetch next batch's indices (hides under the math below)
        if (bt + 1 < NBATCH && e0 + 8 < E)
            idx = load_idx8(src, dst, e0 + 8, E, lid);

#pragma unroll
        for (int b = 0; b < 2; b++) {
            float acc = 0.f;
            const uint32_t* plo = (const uint32_t*)&pv[b][0];
            const uint32_t* qlo = (const uint32_t*)&qv[b][0];
            const uint32_t* phi = (const uint32_t*)&pv[b][1];
            const uint32_t* qhi = (const uint32_t*)&qv[b][1];
#pragma unroll
            for (int i = 0; i < 4; i++) {
                __nv_bfloat162 h = __hmax2(
                    __hadd2(*(const __nv_bfloat162*)&plo[i],
                            *(const __nv_bfloat162*)&qlo[i]), zero2);
                float2 hf = __bfloat1622float2(h);
                acc = fmaf(hf.x, wlo[2 * i], acc);
                acc = fmaf(hf.y, wlo[2 * i + 1], acc);
            }
#pragma unroll
            for (int i = 0; i < 4; i++) {
                __nv_bfloat162 h = __hmax2(
                    __hadd2(*(const __nv_bfloat162*)&phi[i],
                            *(const __nv_bfloat162*)&qhi[i]), zero2);
                float2 hf = __bfloat1622float2(h);
                acc = fmaf(hf.x, whi[2 * i], acc);
                acc = fmaf(hf.y, whi[2 * i + 1], acc);
            }
#pragma unroll
            for (int d = 1; d <= 4; d <<= 1)
                acc += __shfl_xor_sync(0xFFFFFFFF, acc, d);
            if (g == 0) {
                int e = e0 + b * 4 + sub;
                if (e < E)
                    out[e] = 1.f / (1.f + __expf(-(acc + b2v)));
            }
        }
    }
}

// ---------------------------------------------------------------------------
extern "C" void kernel_launch(void* const* d_in, const int* in_sizes, int n_in,
                              void* d_out, int out_size) {
    const int*   src   = (const int*)d_in[0];
    const int*   dst   = (const int*)d_in[1];
    const float* feats = (const float*)d_in[2];
    const float* W1    = (const float*)d_in[3];
    const float* b1    = (const float*)d_in[4];
    const float* W2    = (const float*)d_in[5];
    const float* b2    = (const float*)d_in[6];
    float* out = (float*)d_out;
    int E = in_sizes[0];
    int nNodes = in_sizes[2] / HDIM;

    cudaFuncSetAttribute(node_gemm_kernel,
                         cudaFuncAttributeMaxDynamicSharedMemorySize, GEMM_SMEM);
    node_gemm_kernel<<<NSM, 512, GEMM_SMEM>>>(feats, W1, b1, nNodes);

    int epb = EW_WARPS * 8 * NBATCH;   // edges per block
    edge_kernel<<<(E + epb - 1) / epb, EW_WARPS * 32>>>(src, dst, W2, b2, out, E);
}

// round 15
// speedup vs baseline: 1.6259x; 1.0372x over previous
#include <cuda_runtime.h>
#include <cuda_bf16.h>
#include <cstdint>

// ============================================================================
// Edge-MLP via algebraic split:
//   concat(f_s,f_d) @ W1^T == f_s @ W1a^T + f_d @ W1b^T
// Pass 1: persistent node GEMM (frozen R13: 64-row tiles, reg-prefetched A,
//         staged coalesced copy-out, b1 folded into P).
// Pass 2: direct-LDG edge kernel, 32 edges/warp, rolled batch loop +
//         launch_bounds(256,4) to hold occupancy at 50%.
// ============================================================================

#define MAX_NODES 100000
#define HDIM 128
#define NSM 148
#define TROWS 64

__device__ __nv_bfloat16 g_P[(size_t)MAX_NODES * HDIM];   // P + b1 (bf16)
__device__ __nv_bfloat16 g_Q[(size_t)MAX_NODES * HDIM];

// ---- pass-1 smem layout ----
#define SA      272u                        // bf16 row: 256 B + 16 pad
#define SSTG    528u                        // stage row: 512 B + 16 pad
#define OFF_W   0u                          // 256 x 128 bf16 Wcat (69632 B)
#define OFF_A   (256u * SA)                 // 69632: 64 x 128 bf16 (17408 B)
#define OFF_B1  (OFF_A + 64u * SA)          // 87040: float[128]
#define OFF_STG (OFF_B1 + 512u)             // 87552: 64 x 528 stage
#define GEMM_SMEM (OFF_STG + 64u * SSTG)    // 121344

// ---------------------------------------------------------------------------
__device__ __forceinline__ uint32_t smem_u32(const void* p) {
    uint32_t a;
    asm("{ .reg .u64 t; cvta.to.shared.u64 t, %1; cvt.u32.u64 %0, t; }" : "=r"(a) : "l"(p));
    return a;
}
__device__ __forceinline__ void ldsm_x4(uint32_t* r, uint32_t addr) {
    asm volatile("ldmatrix.sync.aligned.m8n8.x4.shared.b16 {%0,%1,%2,%3}, [%4];"
                 : "=r"(r[0]), "=r"(r[1]), "=r"(r[2]), "=r"(r[3]) : "r"(addr));
}
__device__ __forceinline__ void mma_bf16(float* c, const uint32_t* a,
                                         uint32_t b0, uint32_t b1) {
    asm volatile(
        "mma.sync.aligned.m16n8k16.row.col.f32.bf16.bf16.f32 "
        "{%0,%1,%2,%3}, {%4,%5,%6,%7}, {%8,%9}, {%0,%1,%2,%3};"
        : "+f"(c[0]), "+f"(c[1]), "+f"(c[2]), "+f"(c[3])
        : "r"(a[0]), "r"(a[1]), "r"(a[2]), "r"(a[3]), "r"(b0), "r"(b1));
}
__device__ __forceinline__ void ldg128_nc(uint4& v, const void* p) {
    asm("ld.global.nc.v4.u32 {%0,%1,%2,%3}, [%4];"
        : "=r"(v.x), "=r"(v.y), "=r"(v.z), "=r"(v.w) : "l"(p));
}
__device__ __forceinline__ void sts32(uint32_t addr, uint32_t v) {
    asm volatile("st.shared.u32 [%0], %1;" :: "r"(addr), "r"(v) : "memory");
}
__device__ __forceinline__ void sts64(uint32_t addr, uint32_t lo, uint32_t hi) {
    asm volatile("st.shared.v2.u32 [%0], {%1, %2};" :: "r"(addr), "r"(lo), "r"(hi) : "memory");
}

// ---------------------------------------------------------------------------
// Pass 1: persistent node GEMM (frozen R13).
// ---------------------------------------------------------------------------
__device__ __forceinline__ void prefetch_A(uint4* pf, const float* __restrict__ feats,
                                           int row0, int nNodes) {
    int tid = threadIdx.x;
#pragma unroll
    for (int k = 0; k < 4; k++) {
        int id = k * 512 + tid;
        int r = id >> 5, c = id & 31;
        int node = row0 + r; if (node >= nNodes) node = nNodes - 1;
        ldg128_nc(pf[k], (const char*)(feats + (size_t)node * HDIM) + c * 16);
    }
}

__global__ __launch_bounds__(512, 1) void node_gemm_kernel(
    const float* __restrict__ feats, const float* __restrict__ W1,
    const float* __restrict__ b1, int nNodes)
{
    extern __shared__ char sm[];
    uint32_t sb = smem_u32(sm);
    int tid = threadIdx.x, wid = tid >> 5, lid = tid & 31;
    int ntiles = (nNodes + TROWS - 1) / TROWS;

    uint4 pf[4];
    if (blockIdx.x < ntiles)
        prefetch_A(pf, feats, blockIdx.x * TROWS, nNodes);

    if (tid < 128) ((float*)(sm + OFF_B1))[tid] = b1[tid];

    for (int idx = tid; idx < 256 * 64; idx += 512) {
        int j = idx >> 6, c2 = idx & 63;
        const float* wrow = W1 + (size_t)(j & 127) * 256 + ((j >> 7) << 7);
        float2 v = *(const float2*)(wrow + c2 * 2);
        *(__nv_bfloat162*)(sm + OFF_W + (uint32_t)j * SA + (uint32_t)c2 * 4u) =
            __floats2bfloat162_rn(v.x, v.y);
    }

    int mw = wid & 3, nw = wid >> 2;
    int mbase = mw * 16, nbase = nw * 64;
    uint32_t a_lane = sb + OFF_A +
        (uint32_t)((mbase + (lid & 15)) * SA + ((lid >> 4) * 8) * 2);
    uint32_t b_lane = sb + OFF_W +
        (uint32_t)((nbase + (lid & 7) + ((lid >> 4) << 3)) * SA +
                   (((lid >> 3) & 1) * 8) * 2);
    uint32_t sts_base = sb + OFF_A;
    __syncthreads();

    for (int t = blockIdx.x; t < ntiles; t += NSM) {
        int row0 = t * TROWS;

#pragma unroll
        for (int k = 0; k < 4; k++) {
            int id = k * 512 + tid;
            int r = id >> 5, c = id & 31;
            const float* v = (const float*)&pf[k];
            __nv_bfloat162 lo = __floats2bfloat162_rn(v[0], v[1]);
            __nv_bfloat162 hi = __floats2bfloat162_rn(v[2], v[3]);
            sts64(sts_base + (uint32_t)r * SA + (uint32_t)c * 8u,
                  *(const uint32_t*)&lo, *(const uint32_t*)&hi);
        }
        __syncthreads();

        if (t + NSM < ntiles)
            prefetch_A(pf, feats, (t + NSM) * TROWS, nNodes);

        float acc[8][4];
#pragma unroll
        for (int nt = 0; nt < 8; nt++)
#pragma unroll
            for (int q = 0; q < 4; q++) acc[nt][q] = 0.f;

#pragma unroll
        for (int ks = 0; ks < 8; ks++) {
            uint32_t koff = (uint32_t)ks * 32u;
            uint32_t a[4], b[4][4];
            ldsm_x4(a, a_lane + koff);
#pragma unroll
            for (int u = 0; u < 4; u++)
                ldsm_x4(b[u], b_lane + koff + (uint32_t)u * (16u * SA));
#pragma unroll
            for (int nt = 0; nt < 8; nt++) {
                int bt = nt >> 1, hi = (nt & 1) << 1;
                mma_bf16(acc[nt], a, b[bt][hi], b[bt][hi + 1]);
            }
        }

        const float* b1s = (const float*)(sm + OFF_B1);
#pragma unroll
        for (int nt = 0; nt < 8; nt++) {
            int r = mbase + (lid >> 2);
            int c0 = nbase + nt * 8 + 2 * (lid & 3);
            int isP = (c0 < 128);
            int cc = c0 & 127;
            float bA = isP ? b1s[cc] : 0.f;
            float bB = isP ? b1s[cc + 1] : 0.f;
            const float* c = acc[nt];
            __nv_bfloat162 v0 = __floats2bfloat162_rn(c[0] + bA, c[1] + bB);
            __nv_bfloat162 v1 = __floats2bfloat162_rn(c[2] + bA, c[3] + bB);
            sts32(sb + OFF_STG + (uint32_t)r * SSTG + (uint32_t)c0 * 2u,
                  *(const uint32_t*)&v0);
            sts32(sb + OFF_STG + (uint32_t)(r + 8) * SSTG + (uint32_t)c0 * 2u,
                  *(const uint32_t*)&v1);
        }
        __syncthreads();

#pragma unroll
        for (int it = 0; it < 4; it++) {
            int id = it * 512 + tid;
            int r = id >> 5, c = id & 31;
            int node = row0 + r;
            if (node < nNodes) {
                uint4 v = *(const uint4*)(sm + OFF_STG + (uint32_t)r * SSTG + (uint32_t)c * 16u);
                __nv_bfloat16* dstb = (c < 16 ? g_P : g_Q) + (size_t)node * HDIM + (c & 15) * 8;
                *(uint4*)dstb = v;
            }
        }
    }
}

// ---------------------------------------------------------------------------
// Pass 2: direct-LDG edge kernel. 32 edges/warp, ROLLED batch loop,
// occupancy pinned to 4 blocks/SM (<=64 regs).
// ---------------------------------------------------------------------------
#define EW_WARPS 8    // 256-thr blocks
#define NBATCH   4    // 8-edge batches per warp

__device__ __forceinline__ int load_idx8(const int* __restrict__ src,
                                         const int* __restrict__ dst,
                                         int e0, int E, int lid) {
    int l = lid & 15;
    int e = e0 + (l & 7); if (e >= E) e = E - 1;
    return (l < 8) ? __ldg(src + e) : __ldg(dst + e);
}

__global__ __launch_bounds__(256, 4) void edge_kernel(
    const int* __restrict__ src, const int* __restrict__ dst,
    const float* __restrict__ W2, const float* __restrict__ b2,
    float* __restrict__ out, int E)
{
    int tid = threadIdx.x, wid = tid >> 5, lid = tid & 31;
    int g = lid & 7, sub = lid >> 3;

    int base = (blockIdx.x * EW_WARPS + wid) * (8 * NBATCH);
    if (base >= E) return;

    // w2: chunk 0 covers cols [g*8, g*8+8), chunk 1 covers [64+g*8, ...)
    float wlo[8], whi[8];
#pragma unroll
    for (int i = 0; i < 4; i++) {
        float2 a = *(const float2*)(W2 + g * 8 + 2 * i);
        float2 b = *(const float2*)(W2 + 64 + g * 8 + 2 * i);
        wlo[2 * i] = a.x; wlo[2 * i + 1] = a.y;
        whi[2 * i] = b.x; whi[2 * i + 1] = b.y;
    }
    float b2v = __ldg(b2);

    int idx = load_idx8(src, dst, base, E, lid);
    const __nv_bfloat162 zero2 = __floats2bfloat162_rn(0.f, 0.f);

#pragma unroll 1
    for (int bt = 0; bt < NBATCH; bt++) {
        int e0 = base + bt * 8;
        if (e0 >= E) break;

        // issue all 8 independent LDG.128 (MLP=8)
        uint4 pv[2][2], qv[2][2];
#pragma unroll
        for (int b = 0; b < 2; b++) {
            int sN = __shfl_sync(0xFFFFFFFF, idx, b * 4 + sub);
            int dN = __shfl_sync(0xFFFFFFFF, idx, 8 + b * 4 + sub);
            const char* pb = (const char*)(g_P + (size_t)sN * HDIM);
            const char* qb = (const char*)(g_Q + (size_t)dN * HDIM);
            ldg128_nc(pv[b][0], pb + g * 16);
            ldg128_nc(pv[b][1], pb + 128 + g * 16);
            ldg128_nc(qv[b][0], qb + g * 16);
            ldg128_nc(qv[b][1], qb + 128 + g * 16);
        }
        // prefetch next batch's indices (hides under the math below)
        if (bt + 1 < NBATCH && e0 + 8 < E)
            idx = load_idx8(src, dst, e0 + 8, E, lid);

#pragma unroll
        for (int b = 0; b < 2; b++) {
            float acc = 0.f;
            const uint32_t* plo = (const uint32_t*)&pv[b][0];
            const uint32_t* qlo = (const uint32_t*)&qv[b][0];
            const uint32_t* phi = (const uint32_t*)&pv[b][1];
            const uint32_t* qhi = (const uint32_t*)&qv[b][1];
#pragma unroll
            for (int i = 0; i < 4; i++) {
                __nv_bfloat162 h = __hmax2(
                    __hadd2(*(const __nv_bfloat162*)&plo[i],
                            *(const __nv_bfloat162*)&qlo[i]), zero2);
                float2 hf = __bfloat1622float2(h);
                acc = fmaf(hf.x, wlo[2 * i], acc);
                acc = fmaf(hf.y, wlo[2 * i + 1], acc);
            }
#pragma unroll
            for (int i = 0; i < 4; i++) {
                __nv_bfloat162 h = __hmax2(
                    __hadd2(*(const __nv_bfloat162*)&phi[i],
                            *(const __nv_bfloat162*)&qhi[i]), zero2);
                float2 hf = __bfloat1622float2(h);
                acc = fmaf(hf.x, whi[2 * i], acc);
                acc = fmaf(hf.y, whi[2 * i + 1], acc);
            }
#pragma unroll
            for (int d = 1; d <= 4; d <<= 1)
                acc += __shfl_xor_sync(0xFFFFFFFF, acc, d);
            if (g == 0) {
                int e = e0 + b * 4 + sub;
                if (e < E)
                    out[e] = 1.f / (1.f + __expf(-(acc + b2v)));
            }
        }
    }
}

// ---------------------------------------------------------------------------
extern "C" void kernel_launch(void* const* d_in, const int* in_sizes, int n_in,
                              void* d_out, int out_size) {
    const int*   src   = (const int*)d_in[0];
    const int*   dst   = (const int*)d_in[1];
    const float* feats = (const float*)d_in[2];
    const float* W1    = (const float*)d_in[3];
    const float* b1    = (const float*)d_in[4];
    const float* W2    = (const float*)d_in[5];
    const float* b2    = (const float*)d_in[6];
    float* out = (float*)d_out;
    int E = in_sizes[0];
    int nNodes = in_sizes[2] / HDIM;

    cudaFuncSetAttribute(node_gemm_kernel,
                         cudaFuncAttributeMaxDynamicSharedMemorySize, GEMM_SMEM);
    node_gemm_kernel<<<NSM, 512, GEMM_SMEM>>>(feats, W1, b1, nNodes);

    int epb = EW_WARPS * 8 * NBATCH;   // edges per block
    edge_kernel<<<(E + epb - 1) / epb, EW_WARPS * 32>>>(src, dst, W2, b2, out, E);
}